// round 2
// baseline (speedup 1.0000x reference)
#include <cuda_runtime.h>
#include <stdint.h>

// BinLinear: out = input @ sign(tanh(weight))
// sign(tanh(w)) = +1 iff w >= 0  (tanh monotone, tanh(0)=0; note -0.0 >= 0 is
// true in IEEE, so we must test v < 0, not the raw sign bit).
// Identity: out[n,o] = rowsum[n] - 2 * sum_{i : w[i,o] < 0} input[n,i]
// Pipeline:
//   K1  : rowsum[n] (warp/row, batched float4 loads) + packed sign mask
//   K1b : per-column classification -> g_sign in {+1, -1, 0=mixed}
//   K2  : streaming broadcast writer (fast path), bitmask correction (general)

#define NROWS 8192
#define K_DIM 2048
#define NOUT  2048
#define WORDS 64            // K_DIM / 32

// Scratch in __device__ globals (allocation is forbidden).
__device__ uint32_t g_mask[NOUT * WORDS];  // [col][word] (column-major words)
__device__ float    g_sign[NOUT];          // +1 / -1 / 0 (mixed)
__device__ float    g_rowsum[NROWS];

// ---------------------------------------------------------------------------
// K1: blocks [0,1024) -> rowsum, one warp per row (8 rows/block).
//     blocks [1024,1152) -> sign mask, 4 columns per thread via float4.
// ---------------------------------------------------------------------------
__global__ void __launch_bounds__(256) k1_kernel(const float* __restrict__ x,
                                                 const float* __restrict__ w) {
    const int b = blockIdx.x;
    if (b < 1024) {
        const int warp = threadIdx.x >> 5;
        const int lane = threadIdx.x & 31;
        const int n = b * 8 + warp;
        const float4* xr = reinterpret_cast<const float4*>(x + (size_t)n * K_DIM);
        // Batch all 16 loads first: maximizes MLP.
        float4 a[16];
#pragma unroll
        for (int k = 0; k < 16; ++k) a[k] = xr[lane + 32 * k];
        float s = 0.0f;
#pragma unroll
        for (int k = 0; k < 16; ++k) s += (a[k].x + a[k].y) + (a[k].z + a[k].w);
#pragma unroll
        for (int o = 16; o; o >>= 1) s += __shfl_xor_sync(0xffffffffu, s, o);
        if (lane == 0) g_rowsum[n] = s;
    } else {
        const int t  = (b - 1024) * 256 + threadIdx.x;  // [0, 32768)
        const int cg = t & 511;   // column group: cols [4cg, 4cg+4)
        const int wd = t >> 9;    // word: input rows [32wd, 32wd+32)
        const int c0 = cg * 4;
        uint32_t m0 = 0, m1 = 0, m2 = 0, m3 = 0;
#pragma unroll
        for (int j = 0; j < 32; ++j) {
            const float4 v = *reinterpret_cast<const float4*>(
                w + (size_t)(wd * 32 + j) * NOUT + c0);
            m0 |= (uint32_t)(v.x < 0.0f) << j;
            m1 |= (uint32_t)(v.y < 0.0f) << j;
            m2 |= (uint32_t)(v.z < 0.0f) << j;
            m3 |= (uint32_t)(v.w < 0.0f) << j;
        }
        g_mask[(c0 + 0) * WORDS + wd] = m0;
        g_mask[(c0 + 1) * WORDS + wd] = m1;
        g_mask[(c0 + 2) * WORDS + wd] = m2;
        g_mask[(c0 + 3) * WORDS + wd] = m3;
    }
}

// ---------------------------------------------------------------------------
// K1b: classify each column: all-positive -> +1, all-negative -> -1, else 0.
// Contiguous uint4 reads thanks to [col][word] mask layout. 8 blocks.
// ---------------------------------------------------------------------------
__global__ void __launch_bounds__(256) k1b_kernel() {
    const int c = blockIdx.x * 256 + threadIdx.x;
    const uint4* mp = reinterpret_cast<const uint4*>(g_mask + (size_t)c * WORDS);
    int cnt = 0;
#pragma unroll
    for (int k = 0; k < 16; ++k) {
        const uint4 v = mp[k];
        cnt += __popc(v.x) + __popc(v.y) + __popc(v.z) + __popc(v.w);
    }
    g_sign[c] = (cnt == 0) ? 1.0f : ((cnt == K_DIM) ? -1.0f : 0.0f);
}

// ---------------------------------------------------------------------------
// K2: broadcast writer. Tile = 256 cols x 128 rows, grid (8, 64).
// Fast path (no mixed columns in tile): pure coalesced float4 stores.
// General path: per-element bitmask correction reading x from global
// (correct for arbitrary weights; never taken for this dataset).
// ---------------------------------------------------------------------------
__global__ void __launch_bounds__(256) k2_kernel(const float* __restrict__ x,
                                                 float* __restrict__ out) {
    __shared__ __align__(16) float ss[256];   // per-column sign
    __shared__ float srs[128];                // per-row rowsum
    const int tid  = threadIdx.x;
    const int col0 = blockIdx.x * 256;
    const int row0 = blockIdx.y * 128;

    const float sgn = g_sign[col0 + tid];
    ss[tid] = sgn;
    if (tid < 128) srs[tid] = g_rowsum[row0 + tid];
    const int anymixed = __syncthreads_or(sgn == 0.0f);

    if (!anymixed) {
        const int rsub = tid >> 6;  // 0..3
        const int cg   = tid & 63;  // float4 column group within tile
        const float4 sv = *reinterpret_cast<const float4*>(&ss[cg * 4]);
#pragma unroll
        for (int it = 0; it < 32; ++it) {
            const int r = it * 4 + rsub;
            const float rs = srs[r];
            float4 o;
            o.x = sv.x * rs; o.y = sv.y * rs; o.z = sv.z * rs; o.w = sv.w * rs;
            *reinterpret_cast<float4*>(
                out + (size_t)(row0 + r) * NOUT + col0 + cg * 4) = o;
        }
    } else {
        const int c = col0 + tid;
        const float mysign = ss[tid];
        for (int r = 0; r < 128; ++r) {
            const int row = row0 + r;
            const float rs = srs[r];
            float val;
            if (mysign != 0.0f) {
                val = mysign * rs;
            } else {
                float corr = 0.0f;
                for (int wd = 0; wd < WORDS; ++wd) {
                    uint32_t m = g_mask[(size_t)c * WORDS + wd];
                    while (m) {
                        const int j = __ffs(m) - 1;
                        m &= m - 1;
                        corr += x[(size_t)row * K_DIM + wd * 32 + j];
                    }
                }
                val = rs - 2.0f * corr;
            }
            out[(size_t)row * NOUT + c] = val;
        }
    }
}

extern "C" void kernel_launch(void* const* d_in, const int* in_sizes, int n_in,
                              void* d_out, int out_size) {
    const float* input  = (const float*)d_in[0];   // [8192, 2048] fp32
    const float* weight = (const float*)d_in[1];   // [2048, 2048] fp32
    float*       out    = (float*)d_out;           // [8192, 2048] fp32
    (void)in_sizes; (void)n_in; (void)out_size;

    k1_kernel<<<1152, 256>>>(input, weight);
    k1b_kernel<<<8, 256>>>();
    k2_kernel<<<dim3(8, 64), 256>>>(input, out);
}

// round 3
// speedup vs baseline: 1.0940x; 1.0940x over previous
#include <cuda_runtime.h>
#include <stdint.h>

// BinLinear: out = input @ sign(tanh(weight))
// sign(tanh(w)) = +1 iff w >= 0  (tanh monotone, tanh(0)=0).
// Identity: out[n,o] = rowsum[n] - 2 * sum_{i : w[i,o] < 0} input[n,i]
// Pipeline:
//   K1  : [256 mask blocks FIRST] packed sign mask (warp = 64 cols x 32 rows)
//         [2048 rowsum blocks] rowsum (2 warps/row, 8 float4 per lane)
//   K1b : per-column classification -> g_sign in {+1, -1, 0=mixed}
//   K2  : streaming broadcast writer (fast path), bitmask correction (general)

#define NROWS 8192
#define K_DIM 2048
#define NOUT  2048
#define WORDS 64            // K_DIM / 32
#define MASK_BLOCKS 256     // 2048 warps: 32 col-tiles x 64 word-tiles

__device__ uint32_t g_mask[NOUT * WORDS];  // [col][word]
__device__ float    g_sign[NOUT];          // +1 / -1 / 0 (mixed)
__device__ float    g_rowsum[NROWS];

// ---------------------------------------------------------------------------
// K1: blocks [0,256): sign mask.   warp covers 64 cols x 32 rows.
//     lane = half*16 + cgi; thread owns 4 cols (one float4) x 16 rows,
//     16 independent float4 loads, halves combined via shfl.
//     blocks [256,2304): rowsum.   64 threads (2 warps) per row, 4 rows/block,
//     8 independent float4 loads per lane.
// ---------------------------------------------------------------------------
__global__ void __launch_bounds__(256) k1_kernel(const float* __restrict__ x,
                                                 const float* __restrict__ w) {
    const int b    = blockIdx.x;
    const int tid  = threadIdx.x;
    const int lane = tid & 31;

    if (b < MASK_BLOCKS) {
        const int mw    = b * 8 + (tid >> 5);  // global mask-warp id [0,2048)
        const int ctile = mw & 31;             // 64-col tile
        const int wtile = mw >> 5;             // 32-row (word) tile
        const int cgi   = lane & 15;
        const int half  = lane >> 4;
        const int col0  = ctile * 64 + cgi * 4;
        const int rbase = wtile * 32 + half * 16;

        const float4* wp = reinterpret_cast<const float4*>(w) + (col0 >> 2);
        // 16 independent loads, batched before use.
        float4 v[16];
#pragma unroll
        for (int j = 0; j < 16; ++j) v[j] = wp[(size_t)(rbase + j) * (NOUT / 4)];
        uint32_t p0 = 0, p1 = 0, p2 = 0, p3 = 0;
#pragma unroll
        for (int j = 0; j < 16; ++j) {
            p0 |= (uint32_t)(v[j].x < 0.0f) << j;
            p1 |= (uint32_t)(v[j].y < 0.0f) << j;
            p2 |= (uint32_t)(v[j].z < 0.0f) << j;
            p3 |= (uint32_t)(v[j].w < 0.0f) << j;
        }
        const uint32_t q0 = __shfl_xor_sync(0xffffffffu, p0, 16);
        const uint32_t q1 = __shfl_xor_sync(0xffffffffu, p1, 16);
        const uint32_t q2 = __shfl_xor_sync(0xffffffffu, p2, 16);
        const uint32_t q3 = __shfl_xor_sync(0xffffffffu, p3, 16);
        if (half == 0) {
            g_mask[(size_t)(col0 + 0) * WORDS + wtile] = p0 | (q0 << 16);
            g_mask[(size_t)(col0 + 1) * WORDS + wtile] = p1 | (q1 << 16);
            g_mask[(size_t)(col0 + 2) * WORDS + wtile] = p2 | (q2 << 16);
            g_mask[(size_t)(col0 + 3) * WORDS + wtile] = p3 | (q3 << 16);
        }
    } else {
        __shared__ float wsum[8];
        const int rb  = b - MASK_BLOCKS;       // [0, 2048)
        const int t64 = tid & 63;
        const int row = rb * 4 + (tid >> 6);
        const float4* xr = reinterpret_cast<const float4*>(x + (size_t)row * K_DIM);

        float4 a[8];
#pragma unroll
        for (int k = 0; k < 8; ++k) a[k] = xr[k * 64 + t64];
        float s = 0.0f;
#pragma unroll
        for (int k = 0; k < 8; ++k) s += (a[k].x + a[k].y) + (a[k].z + a[k].w);
#pragma unroll
        for (int o = 16; o; o >>= 1) s += __shfl_xor_sync(0xffffffffu, s, o);
        if (lane == 0) wsum[tid >> 5] = s;
        __syncthreads();
        if (tid < 4) g_rowsum[rb * 4 + tid] = wsum[2 * tid] + wsum[2 * tid + 1];
    }
}

// ---------------------------------------------------------------------------
// K1b: classify each column: all-positive -> +1, all-negative -> -1, else 0.
// ---------------------------------------------------------------------------
__global__ void __launch_bounds__(256) k1b_kernel() {
    const int c = blockIdx.x * 256 + threadIdx.x;
    const uint4* mp = reinterpret_cast<const uint4*>(g_mask + (size_t)c * WORDS);
    int cnt = 0;
#pragma unroll
    for (int k = 0; k < 16; ++k) {
        const uint4 v = mp[k];
        cnt += __popc(v.x) + __popc(v.y) + __popc(v.z) + __popc(v.w);
    }
    g_sign[c] = (cnt == 0) ? 1.0f : ((cnt == K_DIM) ? -1.0f : 0.0f);
}

// ---------------------------------------------------------------------------
// K2: broadcast writer. Tile = 256 cols x 128 rows, grid (8, 64) = 512 blocks.
// Fast path: pure coalesced float4 store stream.
// General path: bitmask correction (correct for arbitrary weights; cold here).
// ---------------------------------------------------------------------------
__global__ void __launch_bounds__(256) k2_kernel(const float* __restrict__ x,
                                                 float* __restrict__ out) {
    __shared__ __align__(16) float ss[256];   // per-column sign
    __shared__ float srs[128];                // per-row rowsum
    const int tid  = threadIdx.x;
    const int col0 = blockIdx.x * 256;
    const int row0 = blockIdx.y * 128;

    const float sgn = g_sign[col0 + tid];
    ss[tid] = sgn;
    if (tid < 128) srs[tid] = g_rowsum[row0 + tid];
    const int anymixed = __syncthreads_or(sgn == 0.0f);

    if (!anymixed) {
        const int rsub = tid >> 6;   // 0..3
        const int cg   = tid & 63;   // float4 column group within tile
        const float4 sv = *reinterpret_cast<const float4*>(&ss[cg * 4]);
        float4* op = reinterpret_cast<float4*>(out + (size_t)row0 * NOUT + col0) + cg;
#pragma unroll
        for (int it = 0; it < 32; ++it) {
            const int r = it * 4 + rsub;
            const float rs = srs[r];
            float4 o;
            o.x = sv.x * rs; o.y = sv.y * rs; o.z = sv.z * rs; o.w = sv.w * rs;
            op[(size_t)r * (NOUT / 4)] = o;
        }
    } else {
        const int c = col0 + tid;
        const float mysign = ss[tid];
        for (int r = 0; r < 128; ++r) {
            const int row = row0 + r;
            const float rs = srs[r];
            float val;
            if (mysign != 0.0f) {
                val = mysign * rs;
            } else {
                float corr = 0.0f;
                for (int wd = 0; wd < WORDS; ++wd) {
                    uint32_t m = g_mask[(size_t)c * WORDS + wd];
                    while (m) {
                        const int j = __ffs(m) - 1;
                        m &= m - 1;
                        corr += x[(size_t)row * K_DIM + wd * 32 + j];
                    }
                }
                val = rs - 2.0f * corr;
            }
            out[(size_t)row * NOUT + c] = val;
        }
    }
}

extern "C" void kernel_launch(void* const* d_in, const int* in_sizes, int n_in,
                              void* d_out, int out_size) {
    const float* input  = (const float*)d_in[0];   // [8192, 2048] fp32
    const float* weight = (const float*)d_in[1];   // [2048, 2048] fp32
    float*       out    = (float*)d_out;           // [8192, 2048] fp32
    (void)in_sizes; (void)n_in; (void)out_size;

    k1_kernel<<<MASK_BLOCKS + 2048, 256>>>(input, weight);
    k1b_kernel<<<NOUT / 256, 256>>>();
    k2_kernel<<<dim3(8, 64), 256>>>(input, out);
}